// round 7
// baseline (speedup 1.0000x reference)
#include <cuda_runtime.h>
#include <cuda_bf16.h>
#include <cstdint>

#define F 128
#define NCTA 148

// ---------------------------------------------------------------------------
// helpers
// ---------------------------------------------------------------------------
__device__ __forceinline__ uint32_t smem_u32(const void* p) {
    uint32_t a;
    asm("{ .reg .u64 t; cvta.to.shared.u64 t, %1; cvt.u32.u64 %0, t; }" : "=r"(a) : "l"(p));
    return a;
}
__device__ __forceinline__ void ldsm_x4(uint32_t* r, uint32_t addr) {
    asm volatile("ldmatrix.sync.aligned.m8n8.x4.shared.b16 {%0,%1,%2,%3}, [%4];"
        : "=r"(r[0]), "=r"(r[1]), "=r"(r[2]), "=r"(r[3]) : "r"(addr));
}
__device__ __forceinline__ void mma_bf16(float4& d, const uint32_t* a, const uint32_t* b) {
    asm volatile("mma.sync.aligned.m16n8k16.row.col.f32.bf16.bf16.f32 "
        "{%0,%1,%2,%3}, {%4,%5,%6,%7}, {%8,%9}, {%0,%1,%2,%3};"
        : "+f"(d.x), "+f"(d.y), "+f"(d.z), "+f"(d.w)
        : "r"(a[0]), "r"(a[1]), "r"(a[2]), "r"(a[3]), "r"(b[0]), "r"(b[1]));
}
__device__ __forceinline__ uint32_t pack_hi2(float a, float b) {
    __nv_bfloat162 t(__float2bfloat16_rn(a), __float2bfloat16_rn(b));
    return *reinterpret_cast<uint32_t*>(&t);
}
__device__ __forceinline__ uint32_t pack_lo2(float a, float b, uint32_t hibits) {
    __nv_bfloat162 h = *reinterpret_cast<__nv_bfloat162*>(&hibits);
    __nv_bfloat162 t(__float2bfloat16_rn(a - __bfloat162float(h.x)),
                     __float2bfloat16_rn(b - __bfloat162float(h.y)));
    return *reinterpret_cast<uint32_t*>(&t);
}
__device__ __forceinline__ void sts64(uint32_t addr, uint32_t v0, uint32_t v1) {
    asm volatile("st.shared.v2.b32 [%0], {%1,%2};" :: "r"(addr), "r"(v0), "r"(v1) : "memory");
}
#define BAR_SYNC(id)   asm volatile("bar.sync %0, 384;"   :: "r"(id) : "memory")
#define BAR_ARRIVE(id) asm volatile("bar.arrive %0, 384;" :: "r"(id) : "memory")

// SW128 blocked-atom offsets. atom = 8 rows x 64 bf16 (1024B).
// W tile: 128x128 (16 atom-rows x 2 atom-cols)
__device__ __forceinline__ uint32_t woff(int row, int col) {
    uint32_t off = (uint32_t)(((row >> 3) + ((col >> 6) << 4)) << 10)
                 + (uint32_t)((row & 7) << 7) + (uint32_t)((col & 63) << 1);
    return off ^ ((off >> 3) & 0x70);
}
// A tile: 32x128 (4 atom-rows x 2 atom-cols) = 8KB
__device__ __forceinline__ uint32_t aoff(int row, int col) {
    uint32_t off = (uint32_t)(((row >> 3) + ((col >> 6) << 2)) << 10)
                 + (uint32_t)((row & 7) << 7) + (uint32_t)((col & 63) << 1);
    return off ^ ((off >> 3) & 0x70);
}

// ---------------------------------------------------------------------------
// fused persistent kernel
// warps 0-3  : MMA consumers (tile 32x128, warp n-slice 32)
// warps 4-11 : scatter producers (4 atoms each per 32-atom tile)
// SMEM: Whi @0 (32K), Wlo @32K, Abuf[2] @64K (16K each: hi +0, lo +8K)
// ---------------------------------------------------------------------------
__global__ void __launch_bounds__(384, 1)
fused_kernel(const float* __restrict__ x,
             const float* __restrict__ alpha,
             const int* __restrict__ idx_i,
             const int* __restrict__ idx_j,
             const float* __restrict__ W,
             float* __restrict__ Y,
             int n_pairs, int n_atoms, int ntiles) {
    extern __shared__ char dsm[];
    __shared__ int s_bounds[11 * 33];

    uint32_t base = (smem_u32(dsm) + 1023u) & ~1023u;
    const uint32_t WHI = base;
    const uint32_t WLO = base + 32768u;
    const uint32_t AB0 = base + 65536u;

    int tid  = threadIdx.x;
    int wid  = tid >> 5;
    int lane = tid & 31;
    int bid  = blockIdx.x;

    // ---- prologue 1: W fp32 -> bf16 hi/lo into SMEM (SW128 layout) ----
    for (int idx = tid; idx < 2048; idx += 384) {
        int row = idx >> 4;
        int c8  = (idx & 15) << 3;
        const float4* wp = (const float4*)(W + row * F + c8);
        float4 v0 = __ldg(wp);
        float4 v1 = __ldg(wp + 1);
        uint32_t h0 = pack_hi2(v0.x, v0.y), h1 = pack_hi2(v0.z, v0.w);
        uint32_t h2 = pack_hi2(v1.x, v1.y), h3 = pack_hi2(v1.z, v1.w);
        uint32_t l0 = pack_lo2(v0.x, v0.y, h0), l1 = pack_lo2(v0.z, v0.w, h1);
        uint32_t l2 = pack_lo2(v1.x, v1.y, h2), l3 = pack_lo2(v1.z, v1.w, h3);
        uint32_t o = woff(row, c8);
        sts64(WHI + o, h0, h1); sts64(WHI + o + 8, h2, h3);
        sts64(WLO + o, l0, l1); sts64(WLO + o + 8, l2, l3);
    }

    // ---- prologue 2: segment bounds for all this CTA's tiles ----
    int nt_cta = (ntiles > bid) ? ((ntiles - bid + NCTA - 1) / NCTA) : 0;
    for (int idx = tid; idx < nt_cta * 33; idx += 384) {
        int k  = idx / 33;
        int jj = idx - k * 33;
        int v  = ((bid + k * NCTA) << 5) + jj;
        int lo = 0, hi = n_pairs;
        while (lo < hi) {
            int mid = (lo + hi) >> 1;
            if (__ldg(idx_i + mid) < v) lo = mid + 1; else hi = mid;
        }
        s_bounds[idx] = lo;
    }
    __syncthreads();

    if (wid < 4) {
        // ================= consumer =================
        int nb    = wid << 5;
        int mrowA = lane & 15;
        int kcolA = (lane >> 4) << 3;
        int nrowB = nb + ((lane >> 4) << 3) + (lane & 7);
        int kcolB = ((lane >> 3) & 1) << 3;

        int it = 0;
        for (int t = bid; t < ntiles; t += NCTA, it++) {
            int b  = it & 1;
            int m0 = t << 5;
            BAR_SYNC(1 + b);
            uint32_t Ab = AB0 + ((uint32_t)b << 14);

            float4 acc[2][4];
            #pragma unroll
            for (int i = 0; i < 2; i++)
                #pragma unroll
                for (int j = 0; j < 4; j++)
                    acc[i][j] = float4{0.f, 0.f, 0.f, 0.f};

            #pragma unroll 1
            for (int kk = 0; kk < 24; kk++) {
                int p  = kk >> 3;
                int k0 = (kk & 7) << 4;
                uint32_t As = Ab + ((p == 2) ? 8192u : 0u);     // hi,hi,lo
                uint32_t Ws = (p == 1) ? WLO : WHI;             // hi,lo,hi

                uint32_t af0[4], af1[4], b0[4], b1[4];
                ldsm_x4(af0, As + aoff(mrowA,      k0 + kcolA));
                ldsm_x4(af1, As + aoff(mrowA + 16, k0 + kcolA));
                ldsm_x4(b0,  Ws + woff(nrowB,      k0 + kcolB));
                ldsm_x4(b1,  Ws + woff(nrowB + 16, k0 + kcolB));

                mma_bf16(acc[0][0], af0, &b0[0]);
                mma_bf16(acc[0][1], af0, &b0[2]);
                mma_bf16(acc[0][2], af0, &b1[0]);
                mma_bf16(acc[0][3], af0, &b1[2]);
                mma_bf16(acc[1][0], af1, &b0[0]);
                mma_bf16(acc[1][1], af1, &b0[2]);
                mma_bf16(acc[1][2], af1, &b1[0]);
                mma_bf16(acc[1][3], af1, &b1[2]);
            }
            BAR_ARRIVE(3 + b);   // buffer free (all SMEM reads issued)

            // epilogue (registers only)
            int rb = m0 + (lane >> 2);
            int cb = nb + ((lane & 3) << 1);
            #pragma unroll
            for (int mf = 0; mf < 2; mf++) {
                int r0 = rb + mf * 16;
                #pragma unroll
                for (int nf = 0; nf < 4; nf++) {
                    int c = cb + nf * 8;
                    if (r0 < n_atoms)
                        *(float2*)(Y + (size_t)r0 * F + c) = float2{acc[mf][nf].x, acc[mf][nf].y};
                    if (r0 + 8 < n_atoms)
                        *(float2*)(Y + (size_t)(r0 + 8) * F + c) = float2{acc[mf][nf].z, acc[mf][nf].w};
                }
            }
        }
    } else {
        // ================= producer =================
        int pw = wid - 4;                 // 0..7
        const float4* x4 = (const float4*)x;

        int it = 0;
        for (int t = bid; t < ntiles; t += NCTA, it++) {
            int b = it & 1;
            if (it >= 2) BAR_SYNC(3 + b);
            uint32_t Ab = AB0 + ((uint32_t)b << 14);
            int bbase = it * 33 + (pw << 2);

            #pragma unroll 1
            for (int a = 0; a < 4; a++) {
                int row = (pw << 2) + a;
                int lo = s_bounds[bbase + a];
                int hi = s_bounds[bbase + a + 1];

                float4 acc = {0.f, 0.f, 0.f, 0.f};
                int p = lo;
                for (; p + 8 <= hi; p += 8) {
                    int   j[8];
                    float al[8];
                    #pragma unroll
                    for (int u = 0; u < 8; u++) {
                        j[u]  = __ldg(idx_j + p + u);
                        al[u] = __ldg(alpha + p + u);
                    }
                    #pragma unroll
                    for (int u = 0; u < 8; u++) {
                        float4 v = __ldg(x4 + (size_t)j[u] * 32 + lane);
                        acc.x = fmaf(al[u], v.x, acc.x);
                        acc.y = fmaf(al[u], v.y, acc.y);
                        acc.z = fmaf(al[u], v.z, acc.z);
                        acc.w = fmaf(al[u], v.w, acc.w);
                    }
                }
                for (; p < hi; p++) {
                    int   j0 = __ldg(idx_j + p);
                    float a0 = __ldg(alpha + p);
                    float4 v = __ldg(x4 + (size_t)j0 * 32 + lane);
                    acc.x = fmaf(a0, v.x, acc.x);
                    acc.y = fmaf(a0, v.y, acc.y);
                    acc.z = fmaf(a0, v.z, acc.z);
                    acc.w = fmaf(a0, v.w, acc.w);
                }

                uint32_t h0 = pack_hi2(acc.x, acc.y);
                uint32_t h1 = pack_hi2(acc.z, acc.w);
                uint32_t l0 = pack_lo2(acc.x, acc.y, h0);
                uint32_t l1 = pack_lo2(acc.z, acc.w, h1);
                uint32_t o = aoff(row, lane << 2);
                sts64(Ab + o, h0, h1);
                sts64(Ab + 8192u + o, l0, l1);
            }
            __threadfence_block();
            BAR_ARRIVE(1 + b);
        }
    }
}

// ---------------------------------------------------------------------------
// launcher
// ---------------------------------------------------------------------------
extern "C" void kernel_launch(void* const* d_in, const int* in_sizes, int n_in,
                              void* d_out, int out_size) {
    const float* x     = (const float*)d_in[0];
    const float* alpha = (const float*)d_in[1];
    const int*   idx_i = (const int*)d_in[2];
    const int*   idx_j = (const int*)d_in[3];
    const float* W     = (const float*)d_in[4];
    float*       Y     = (float*)d_out;

    int n_atoms = in_sizes[0] / F;
    int n_pairs = in_sizes[1];
    int ntiles  = (n_atoms + 31) / 32;

    int smem = 65536 + 2 * 16384 + 1024;   // W hi/lo + 2 A buffers + align pad
    cudaFuncSetAttribute(fused_kernel, cudaFuncAttributeMaxDynamicSharedMemorySize, smem);
    int grid = (ntiles < NCTA) ? ntiles : NCTA;
    fused_kernel<<<grid, 384, smem>>>(x, alpha, idx_i, idx_j, W, Y,
                                      n_pairs, n_atoms, ntiles);
}